// round 9
// baseline (speedup 1.0000x reference)
#include <cuda_runtime.h>
#include <cuda_fp16.h>
#include <math.h>
#include <stdint.h>

#define NN 100000
#define EE 1600000
#define GG 2048
#define NCOUT 204

// ---------------- static scratch (no runtime allocation allowed) ----------------
__device__ __half g_bufT[NN * 128];      // t for layer 0 (GEMM input, fp16)
__device__ __half g_bufY[NN * 128];      // y (pre-BN GEMM output, fp16)
__device__ __half g_bufX[NN * 128];      // x = relu(bn(y)) (fp16)
__device__ int    g_rowptr[NN + 1];
__device__ int    g_cursor[NN];
__device__ int    g_col[EE];
__device__ float  g_stats[8 * 1024];     // per-layer [sum(0..C) | sumsq(C..2C)]
__device__ float  g_xg[GG * 128];
__device__ float  g_m1[GG * 512];
__device__ float  g_m2[GG * 256];
__device__ __half g_wt[128 * 128];       // W^T fp16 (n-major [n][k])

// ---------------- W convert (+ first-call scratch zeroing; replaces memsets) ----------
__global__ void wcvt_kernel(const float* __restrict__ W, int K, __half* __restrict__ Wt,
                            int init) {
    int i = blockIdx.x * blockDim.x + threadIdx.x;   // 16384 threads
    if (init) {
        for (int j = i; j < NN + 1; j += 16384) g_rowptr[j] = 0;
        for (int j = i; j < 8 * 1024; j += 16384) g_stats[j] = 0.f;
    }
    if (i < 128 * 128) {
        int k = i >> 7, n = i & 127;
        float w = (k < K) ? W[k * 128 + n] : 0.f;   // zero-pad K
        Wt[n * 128 + k] = __float2half(w);
    }
}

// ---------------- CSR build ----------------
__global__ void hist_kernel(const int* __restrict__ edst) {
    int e = blockIdx.x * blockDim.x + threadIdx.x;
    if (e < NN) g_cursor[e] = 0;                    // fold cursor zeroing in
    if (e < EE) atomicAdd(&g_rowptr[edst[e] + 1], 1);
}

// inclusive scan, single block of 1024, chunked (2 passes over data)
__global__ void scan_kernel(int* a, int n) {
    __shared__ int s[1024];
    int tid = threadIdx.x;
    int chunk = (n + 1023) >> 10;
    int beg = tid * chunk;
    int end = beg + chunk; if (end > n) end = n;
    int sum = 0;
    for (int i = beg; i < end; ++i) sum += a[i];
    s[tid] = sum;
    __syncthreads();
    for (int off = 1; off < 1024; off <<= 1) {
        int t = (tid >= off) ? s[tid - off] : 0;
        __syncthreads();
        s[tid] += t;
        __syncthreads();
    }
    int run = (tid > 0) ? s[tid - 1] : 0;
    for (int i = beg; i < end; ++i) { run += a[i]; a[i] = run; }
}

__global__ void fill_kernel(const int* __restrict__ esrc, const int* __restrict__ edst) {
    int e = blockIdx.x * blockDim.x + threadIdx.x;
    if (e >= EE) return;
    int d = edst[e];
    int pos = atomicAdd(&g_cursor[d], 1);
    g_col[g_rowptr[d] + pos] = esrc[e];
}

// ---------------- layer 0 aggregation: t = 2*h + sum_in(h), 78 dims -> fp16 -------------
__global__ void agg0_kernel(const float* __restrict__ H) {
    int w = (blockIdx.x * blockDim.x + threadIdx.x) >> 5;
    if (w >= NN) return;
    int lid = threadIdx.x & 31;
    const float* hr = H + (size_t)w * 78;
    float a0 = 2.f * hr[lid];
    float a1 = 2.f * hr[lid + 32];
    float a2 = (lid < 14) ? 2.f * hr[lid + 64] : 0.f;
    int beg = g_rowptr[w], end = g_rowptr[w + 1];
    int j = beg;
    for (; j + 4 <= end; j += 4) {
        int s[4];
#pragma unroll
        for (int u = 0; u < 4; ++u) s[u] = g_col[j + u];
        float x[4], y[4], z[4];
#pragma unroll
        for (int u = 0; u < 4; ++u) {
            const float* hp = H + (size_t)s[u] * 78;
            x[u] = hp[lid];
            y[u] = hp[lid + 32];
            z[u] = (lid < 14) ? hp[lid + 64] : 0.f;
        }
        a0 += (x[0] + x[1]) + (x[2] + x[3]);
        a1 += (y[0] + y[1]) + (y[2] + y[3]);
        a2 += (z[0] + z[1]) + (z[2] + z[3]);
    }
    for (; j < end; ++j) {
        const float* hs = H + (size_t)g_col[j] * 78;
        a0 += hs[lid];
        a1 += hs[lid + 32];
        if (lid < 14) a2 += hs[lid + 64];
    }
    __half* t = g_bufT + (size_t)w * 128;
    t[lid] = __float2half(a0);
    t[lid + 32] = __float2half(a1);
    t[lid + 64] = (lid < 14) ? __float2half(a2) : __float2half(0.f);
    t[lid + 96] = __float2half(0.f);   // zero-pad K 78..127
}

// ---------------- fused: X = relu(bn(Y)) fp16  +  W convert (first 64 blocks) ------------
__global__ void bnw_kernel(const __half* __restrict__ Yin, __half* __restrict__ Xout,
                           const float* __restrict__ stats, const float* __restrict__ gamma,
                           const float* __restrict__ beta,
                           const float* __restrict__ W, __half* __restrict__ Wt) {
    __shared__ float ssc[128], ssh[128];
    int tid = threadIdx.x;
    if (blockIdx.x < 64) {                     // fold W^T fp16 convert in
        int i = blockIdx.x * 256 + tid;
        int k = i >> 7, n = i & 127;
        Wt[n * 128 + k] = __float2half(W[k * 128 + n]);
    }
    if (tid < 128) {
        const float invn = 1.f / NN;
        float mu = stats[tid] * invn;
        float var = stats[128 + tid] * invn - mu * mu;
        float s = gamma[tid] * rsqrtf(var + 1e-5f);
        ssc[tid] = s;
        ssh[tid] = beta[tid] - mu * s;
    }
    __syncthreads();
    const __half2* Y2 = (const __half2*)Yin;
    __half2* X2 = (__half2*)Xout;
    int total = NN * 64;
    for (int i = blockIdx.x * blockDim.x + tid; i < total; i += gridDim.x * blockDim.x) {
        int c0 = (i & 63) * 2;
        float2 f = __half22float2(Y2[i]);
        float v0 = fmaxf(0.f, f.x * ssc[c0] + ssh[c0]);
        float v1 = fmaxf(0.f, f.y * ssc[c0 + 1] + ssh[c0 + 1]);
        X2[i] = __floats2half2_rn(v0, v1);
    }
}

// ---------------- readout: xg[g] = sum relu(bn(y)) over rows of graph g (gid sorted) -----
__global__ void readout_kernel(const __half* __restrict__ Yin, const int* __restrict__ gid,
                               float* __restrict__ xg, const float* __restrict__ stats,
                               const float* __restrict__ gamma, const float* __restrict__ beta) {
    __shared__ float ssc[128], ssh[128];
    int tid = threadIdx.x;       // 128 threads = one column each
    {
        const float invn = 1.f / NN;
        float mu = stats[tid] * invn;
        float var = stats[128 + tid] * invn - mu * mu;
        float s = gamma[tid] * rsqrtf(var + 1e-5f);
        ssc[tid] = s;
        ssh[tid] = beta[tid] - mu * s;
    }
    __syncthreads();
    int g = blockIdx.x;          // 2048 blocks
    int lo = 0, hi = NN;
    while (lo < hi) { int mid = (lo + hi) >> 1; if (gid[mid] < g) lo = mid + 1; else hi = mid; }
    int beg = lo;
    hi = NN;
    while (lo < hi) { int mid = (lo + hi) >> 1; if (gid[mid] < g + 1) lo = mid + 1; else hi = mid; }
    int end = lo;
    float sc = ssc[tid], sh = ssh[tid];
    float acc = 0.f;
    for (int r = beg; r < end; ++r)
        acc += fmaxf(0.f, __half2float(Yin[(size_t)r * 128 + tid]) * sc + sh);
    xg[(size_t)g * 128 + tid] = acc;
}

// ---------------- HMMA fp16 helper ----------------
__device__ __forceinline__ void mma16816(float c[4], uint32_t a0, uint32_t a1,
                                         uint32_t a2, uint32_t a3,
                                         uint32_t b0, uint32_t b1) {
    asm volatile(
        "mma.sync.aligned.m16n8k16.row.col.f32.f16.f16.f32 "
        "{%0,%1,%2,%3}, {%4,%5,%6,%7}, {%8,%9}, {%0,%1,%2,%3};"
        : "+f"(c[0]), "+f"(c[1]), "+f"(c[2]), "+f"(c[3])
        : "r"(a0), "r"(a1), "r"(a2), "r"(a3), "r"(b0), "r"(b1));
}

// ---------------- fused gather+GEMM: y = (2x + Agg(x)) @ W + 2b ----------------
// gather=1: A tile built by in-CTA CSR gather from X (no T buffer).
// gather=0: A tile loaded from T (layer 0).
// 128x128 CTA tile, 8 warps as 4(m)x2(n), fp16 single K-stage. Fused bias + BN stats.
#define PITCH 136
__global__ void __launch_bounds__(256, 2) gemm_mma_kernel(
    const __half* __restrict__ Xin, int gather, const __half* __restrict__ T,
    const __half* __restrict__ Wt, const float* __restrict__ bias, float bscale,
    __half* __restrict__ Y, float* __restrict__ stats) {
    extern __shared__ char smem[];
    __half* Ah = (__half*)smem;                 // [128][136]
    __half* Bh = Ah + 128 * PITCH;              // [128][136]
    float* sbias = (float*)(Bh + 128 * PITCH);  // 128
    float* sstat = sbias + 128;                 // 256 (sum|sq)

    int tid = threadIdx.x;
    int lane = tid & 31, wid = tid >> 5;
    int q = lane & 3, rsel = lane >> 2;
    int mw = wid & 3, nw = wid >> 2;
    int m0 = mw * 32, n0 = nw * 64;
    int row0 = blockIdx.x * 128;

    if (tid < 128) sbias[tid] = bscale * bias[tid];
    sstat[tid] = 0.f;

    // ---- B tile (always from global Wt) ----
    for (int idx = tid; idx < 2048; idx += 256) {
        int r = idx >> 4, c8 = idx & 15;
        *(uint4*)&Bh[r * PITCH + c8 * 8] = *(const uint4*)&g_wt[r * 128 + c8 * 8];
    }

    // ---- A tile ----
    if (gather) {
        // warp wid aggregates nodes row0+wid*16 .. +15 directly from X via CSR
        const uint2* X2 = (const uint2*)Xin;
        for (int i = 0; i < 16; ++i) {
            int r = wid * 16 + i;
            int gr = row0 + r;
            float a0 = 0.f, a1 = 0.f, a2 = 0.f, a3 = 0.f;
            if (gr < NN) {
                uint2 self = X2[(size_t)gr * 32 + lane];
                float2 f0 = __half22float2(*(__half2*)&self.x);
                float2 f1 = __half22float2(*(__half2*)&self.y);
                a0 = 2.f * f0.x; a1 = 2.f * f0.y; a2 = 2.f * f1.x; a3 = 2.f * f1.y;
                int beg = g_rowptr[gr], end = g_rowptr[gr + 1];
                int j = beg;
                for (; j + 8 <= end; j += 8) {
                    int s[8];
#pragma unroll
                    for (int u = 0; u < 8; ++u) s[u] = g_col[j + u];
                    uint2 rr[8];
#pragma unroll
                    for (int u = 0; u < 8; ++u) rr[u] = X2[(size_t)s[u] * 32 + lane];
#pragma unroll
                    for (int u = 0; u < 8; u += 2) {
                        __half2 p0 = __hadd2(*(__half2*)&rr[u].x, *(__half2*)&rr[u + 1].x);
                        __half2 p1 = __hadd2(*(__half2*)&rr[u].y, *(__half2*)&rr[u + 1].y);
                        float2 u0 = __half22float2(p0), u1 = __half22float2(p1);
                        a0 += u0.x; a1 += u0.y; a2 += u1.x; a3 += u1.y;
                    }
                }
                for (; j < end; ++j) {
                    uint2 r0 = X2[(size_t)g_col[j] * 32 + lane];
                    float2 u0 = __half22float2(*(__half2*)&r0.x);
                    float2 u1 = __half22float2(*(__half2*)&r0.y);
                    a0 += u0.x; a1 += u0.y; a2 += u1.x; a3 += u1.y;
                }
            }
            uint2 o;
            *(__half2*)&o.x = __floats2half2_rn(a0, a1);
            *(__half2*)&o.y = __floats2half2_rn(a2, a3);
            *(uint2*)&Ah[r * PITCH + lane * 4] = o;
        }
    } else {
        for (int idx = tid; idx < 2048; idx += 256) {
            int r = idx >> 4, c8 = idx & 15;
            int gr = row0 + r;
            uint4 v = make_uint4(0u, 0u, 0u, 0u);
            if (gr < NN) v = *(const uint4*)&T[(size_t)gr * 128 + c8 * 8];
            *(uint4*)&Ah[r * PITCH + c8 * 8] = v;
        }
    }
    __syncthreads();

    float acc[2][8][4];
#pragma unroll
    for (int i = 0; i < 2; ++i)
#pragma unroll
        for (int j = 0; j < 8; ++j)
#pragma unroll
            for (int p = 0; p < 4; ++p) acc[i][j][p] = 0.f;

#pragma unroll
    for (int ks = 0; ks < 128; ks += 16) {
        uint32_t a[2][4];
#pragma unroll
        for (int i = 0; i < 2; ++i) {
            const __half* ar = Ah + (m0 + i * 16 + rsel) * PITCH + ks + 2 * q;
            a[i][0] = *(const uint32_t*)ar;
            a[i][1] = *(const uint32_t*)(ar + 8 * PITCH);
            a[i][2] = *(const uint32_t*)(ar + 8);
            a[i][3] = *(const uint32_t*)(ar + 8 * PITCH + 8);
        }
#pragma unroll
        for (int j = 0; j < 8; ++j) {
            const __half* br = Bh + (n0 + j * 8 + rsel) * PITCH + ks + 2 * q;
            uint32_t b0 = *(const uint32_t*)br;
            uint32_t b1 = *(const uint32_t*)(br + 8);
            mma16816(acc[0][j], a[0][0], a[0][1], a[0][2], a[0][3], b0, b1);
            mma16816(acc[1][j], a[1][0], a[1][1], a[1][2], a[1][3], b0, b1);
        }
    }

    // epilogue: bias, fp16 store, BN stats (from exact fp32 values)
#pragma unroll
    for (int i = 0; i < 2; ++i) {
        int r_lo = row0 + m0 + i * 16 + rsel, r_hi = r_lo + 8;
        bool vlo = r_lo < NN, vhi = r_hi < NN;
#pragma unroll
        for (int j = 0; j < 8; ++j) {
            int c0 = n0 + j * 8 + 2 * q;
            float b0 = sbias[c0], b1 = sbias[c0 + 1];
            float v00 = vlo ? acc[i][j][0] + b0 : 0.f;
            float v01 = vlo ? acc[i][j][1] + b1 : 0.f;
            float v10 = vhi ? acc[i][j][2] + b0 : 0.f;
            float v11 = vhi ? acc[i][j][3] + b1 : 0.f;
            if (vlo) *(__half2*)&Y[(size_t)r_lo * 128 + c0] = __floats2half2_rn(v00, v01);
            if (vhi) *(__half2*)&Y[(size_t)r_hi * 128 + c0] = __floats2half2_rn(v10, v11);
            float s0 = v00 + v10, s1 = v01 + v11;
            float q0 = v00 * v00 + v10 * v10, q1 = v01 * v01 + v11 * v11;
#pragma unroll
            for (int off = 4; off <= 16; off <<= 1) {
                s0 += __shfl_xor_sync(0xFFFFFFFFu, s0, off);
                s1 += __shfl_xor_sync(0xFFFFFFFFu, s1, off);
                q0 += __shfl_xor_sync(0xFFFFFFFFu, q0, off);
                q1 += __shfl_xor_sync(0xFFFFFFFFu, q1, off);
            }
            if (rsel == 0) {
                atomicAdd(&sstat[c0], s0);
                atomicAdd(&sstat[c0 + 1], s1);
                atomicAdd(&sstat[128 + c0], q0);
                atomicAdd(&sstat[128 + c0 + 1], q1);
            }
        }
    }
    __syncthreads();
    atomicAdd(&stats[tid], sstat[tid]);
}

// ---------------- small MLP GEMM (thread-per-output) ----------------
__global__ void gemm_small_kernel(const float* __restrict__ X, const float* __restrict__ W,
                                  const float* __restrict__ bias, int R, int K, int C,
                                  float* __restrict__ Y, float* __restrict__ stats) {
    int c = blockIdx.x * 32 + (threadIdx.x & 31);
    int r = blockIdx.y * 8 + (threadIdx.x >> 5);
    if (c >= C || r >= R) return;
    float acc = bias[c];
    const float* xr = X + (size_t)r * K;
    for (int k = 0; k < K; ++k) acc = fmaf(xr[k], W[(size_t)k * C + c], acc);
    Y[(size_t)r * C + c] = acc;
    atomicAdd(&stats[c], acc);
    atomicAdd(&stats[C + c], acc * acc);
}

// norm+relu with BN finalize folded in
__global__ void norm_relu_kernel(float* __restrict__ Y, const float* __restrict__ stats,
                                 const float* __restrict__ gamma, const float* __restrict__ beta,
                                 float invn, int total, int C) {
    int i = blockIdx.x * blockDim.x + threadIdx.x;
    if (i >= total) return;
    int c = i % C;
    float mu = stats[c] * invn;
    float var = stats[C + c] * invn - mu * mu;
    float s = gamma[c] * rsqrtf(var + 1e-5f);
    float v = (Y[i] - mu) * s + beta[c];
    Y[i] = fmaxf(v, 0.f);
}

__global__ void fc2_kernel(const float* __restrict__ X, const float* __restrict__ W,
                           const float* __restrict__ bias, float* __restrict__ out) {
    int c = blockIdx.x * 32 + (threadIdx.x & 31);
    int g = blockIdx.y * 8 + (threadIdx.x >> 5);
    if (c >= NCOUT || g >= GG) return;
    float acc = bias[204 + c];
    const float* xr = X + (size_t)g * 256;
    for (int k = 0; k < 256; ++k) acc = fmaf(xr[k], W[(size_t)k * 408 + 204 + c], acc);
    out[(size_t)g * NCOUT + c] = 1.f / (1.f + expf(-acc));
}

// ---------------- host orchestration ----------------
extern "C" void kernel_launch(void* const* d_in, const int* in_sizes, int n_in,
                              void* d_out, int out_size) {
    const float* h        = (const float*)d_in[0];
    const int*   esrc     = (const int*)d_in[1];
    const int*   edst     = (const int*)d_in[2];
    const int*   gid      = (const int*)d_in[3];
    const float* W1       = (const float*)d_in[4];
    const float* b1       = (const float*)d_in[5];
    const float* g1_gamma = (const float*)d_in[6];
    const float* g1_beta  = (const float*)d_in[7];
    const float* Wg       = (const float*)d_in[8];
    const float* bg       = (const float*)d_in[9];
    const float* gg       = (const float*)d_in[10];
    const float* gb       = (const float*)d_in[11];
    const float* fc1_W    = (const float*)d_in[12];
    const float* fc1_b    = (const float*)d_in[13];
    const float* bn1_g    = (const float*)d_in[14];
    const float* bn1_b    = (const float*)d_in[15];
    const float* lin_W    = (const float*)d_in[16];
    const float* lin_b    = (const float*)d_in[17];
    const float* lbn_g    = (const float*)d_in[18];
    const float* lbn_b    = (const float*)d_in[19];
    const float* fc2_W    = (const float*)d_in[20];
    const float* fc2_b    = (const float*)d_in[21];
    float* out = (float*)d_out;

    float *stats, *xg, *m1, *m2;
    __half *bufT, *bufY, *bufX, *wt;
    int *rowptr;
    cudaGetSymbolAddress((void**)&bufT, g_bufT);
    cudaGetSymbolAddress((void**)&bufY, g_bufY);
    cudaGetSymbolAddress((void**)&bufX, g_bufX);
    cudaGetSymbolAddress((void**)&stats, g_stats);
    cudaGetSymbolAddress((void**)&xg, g_xg);
    cudaGetSymbolAddress((void**)&m1, g_m1);
    cudaGetSymbolAddress((void**)&m2, g_m2);
    cudaGetSymbolAddress((void**)&rowptr, g_rowptr);
    cudaGetSymbolAddress((void**)&wt, g_wt);

    const int SMEMMA = 2 * 128 * PITCH * 2 + 128 * 4 + 256 * 4;   // 71168
    cudaFuncSetAttribute(gemm_mma_kernel, cudaFuncAttributeMaxDynamicSharedMemorySize, SMEMMA);

    const int WB = (NN * 32 + 255) / 256;   // warp-per-node grids
    const int EB = (EE + 255) / 256;
    const int GBt = (NN + 127) / 128;       // 782 GEMM tiles
    const int BNB = 6250;

    // ---- CSR build + layer 0 ----
    wcvt_kernel<<<64, 256>>>(W1, 78, wt, 1);     // also zeroes rowptr + stats
    hist_kernel<<<EB, 256>>>(edst);              // also zeroes cursor
    scan_kernel<<<1, 1024>>>(rowptr, NN + 1);
    fill_kernel<<<EB, 256>>>(esrc, edst);
    agg0_kernel<<<WB, 256>>>(h);
    gemm_mma_kernel<<<GBt, 256, SMEMMA>>>(bufX, 0, bufT, wt, b1, 2.f, bufY, stats);

    // ---- layers 1..4: bnw (X + W^T) -> fused gather+GEMM ----
    const float* gmas[5] = {g1_gamma, gg, gg + 128, gg + 256, gg + 384};
    const float* btas[5] = {g1_beta,  gb, gb + 128, gb + 256, gb + 384};
    for (int l = 0; l < 4; ++l) {
        float* stPrev = stats + l * 1024;
        float* st = stats + (l + 1) * 1024;
        bnw_kernel<<<BNB, 256>>>(bufY, bufX, stPrev, gmas[l], btas[l],
                                 Wg + (size_t)l * 128 * 128, wt);
        gemm_mma_kernel<<<GBt, 256, SMEMMA>>>(bufX, 1, bufT, wt, bg + l * 128, 2.f, bufY, st);
    }

    // ---- fused BN + sorted segment-sum readout ----
    readout_kernel<<<GG, 128>>>(bufY, gid, xg, stats + 4 * 1024, gmas[4], btas[4]);

    // ---- MLP head ----
    float* st5 = stats + 5 * 1024;
    float* st6 = stats + 6 * 1024;
    gemm_small_kernel<<<dim3(512 / 32, GG / 8), 256>>>(xg, fc1_W, fc1_b, GG, 128, 512, m1, st5);
    norm_relu_kernel<<<(GG * 512 + 255) / 256, 256>>>(m1, st5, bn1_g, bn1_b, 1.f / GG,
                                                      GG * 512, 512);

    gemm_small_kernel<<<dim3(256 / 32, GG / 8), 256>>>(m1, lin_W, lin_b, GG, 512, 256, m2, st6);
    norm_relu_kernel<<<(GG * 256 + 255) / 256, 256>>>(m2, st6, lbn_g, lbn_b, 1.f / GG,
                                                      GG * 256, 256);

    fc2_kernel<<<dim3(7, GG / 8), 256>>>(m2, fc2_W, fc2_b, out);
}

// round 10
// speedup vs baseline: 1.1731x; 1.1731x over previous
#include <cuda_runtime.h>
#include <cuda_fp16.h>
#include <math.h>
#include <stdint.h>

#define NN 100000
#define EE 1600000
#define GG 2048
#define NCOUT 204

// ---------------- static scratch (no runtime allocation allowed) ----------------
__device__ __half g_bufT[NN * 128];      // t (GEMM input, fp16)
__device__ __half g_bufY[NN * 128];      // y (pre-BN GEMM output, fp16)
__device__ __half g_bufX[NN * 128];      // x = relu(bn(y)) (fp16)
__device__ int    g_rowptr[NN + 1];
__device__ int    g_cursor[NN];
__device__ int    g_col[EE];
__device__ float  g_stats[8 * 1024];     // per-layer [sum(0..C) | sumsq(C..2C)]
__device__ float  g_xg[GG * 128];
__device__ float  g_m1[GG * 512];
__device__ float  g_m2[GG * 256];
__device__ __half g_wt[128 * 128];       // W^T fp16 (n-major [n][k])

// ---------------- W convert (+ first-call scratch zeroing; replaces memsets) ----------
__global__ void wcvt_kernel(const float* __restrict__ W, int K, __half* __restrict__ Wt,
                            int init) {
    int i = blockIdx.x * blockDim.x + threadIdx.x;   // 16384 threads
    if (init) {
        for (int j = i; j < NN + 1; j += 16384) g_rowptr[j] = 0;
        for (int j = i; j < 8 * 1024; j += 16384) g_stats[j] = 0.f;
    }
    if (i < 128 * 128) {
        int k = i >> 7, n = i & 127;
        float w = (k < K) ? W[k * 128 + n] : 0.f;   // zero-pad K
        Wt[n * 128 + k] = __float2half(w);
    }
}

// ---------------- CSR build ----------------
__global__ void hist_kernel(const int* __restrict__ edst) {
    int e = blockIdx.x * blockDim.x + threadIdx.x;
    if (e < NN) g_cursor[e] = 0;                    // fold cursor zeroing in
    if (e < EE) atomicAdd(&g_rowptr[edst[e] + 1], 1);
}

// inclusive scan, single block of 1024, chunked (2 passes over data)
__global__ void scan_kernel(int* a, int n) {
    __shared__ int s[1024];
    int tid = threadIdx.x;
    int chunk = (n + 1023) >> 10;
    int beg = tid * chunk;
    int end = beg + chunk; if (end > n) end = n;
    int sum = 0;
    for (int i = beg; i < end; ++i) sum += a[i];
    s[tid] = sum;
    __syncthreads();
    for (int off = 1; off < 1024; off <<= 1) {
        int t = (tid >= off) ? s[tid - off] : 0;
        __syncthreads();
        s[tid] += t;
        __syncthreads();
    }
    int run = (tid > 0) ? s[tid - 1] : 0;
    for (int i = beg; i < end; ++i) { run += a[i]; a[i] = run; }
}

__global__ void fill_kernel(const int* __restrict__ esrc, const int* __restrict__ edst) {
    int e = blockIdx.x * blockDim.x + threadIdx.x;
    if (e >= EE) return;
    int d = edst[e];
    int pos = atomicAdd(&g_cursor[d], 1);
    g_col[g_rowptr[d] + pos] = esrc[e];
}

// ---------------- layer 0 aggregation: t = 2*h + sum_in(h), 78 dims -> fp16 (pad to 80) --
__global__ void agg0_kernel(const float* __restrict__ H) {
    int w = (blockIdx.x * blockDim.x + threadIdx.x) >> 5;
    if (w >= NN) return;
    int lid = threadIdx.x & 31;
    const float* hr = H + (size_t)w * 78;
    float a0 = 2.f * hr[lid];
    float a1 = 2.f * hr[lid + 32];
    float a2 = (lid < 14) ? 2.f * hr[lid + 64] : 0.f;
    int beg = g_rowptr[w], end = g_rowptr[w + 1];
    int j = beg;
    for (; j + 4 <= end; j += 4) {
        int s[4];
#pragma unroll
        for (int u = 0; u < 4; ++u) s[u] = g_col[j + u];
        float x[4], y[4], z[4];
#pragma unroll
        for (int u = 0; u < 4; ++u) {
            const float* hp = H + (size_t)s[u] * 78;
            x[u] = hp[lid];
            y[u] = hp[lid + 32];
            z[u] = (lid < 14) ? hp[lid + 64] : 0.f;
        }
        a0 += (x[0] + x[1]) + (x[2] + x[3]);
        a1 += (y[0] + y[1]) + (y[2] + y[3]);
        a2 += (z[0] + z[1]) + (z[2] + z[3]);
    }
    for (; j < end; ++j) {
        const float* hs = H + (size_t)g_col[j] * 78;
        a0 += hs[lid];
        a1 += hs[lid + 32];
        if (lid < 14) a2 += hs[lid + 64];
    }
    __half* t = g_bufT + (size_t)w * 128;
    t[lid] = __float2half(a0);
    t[lid + 32] = __float2half(a1);
    if (lid < 16) t[lid + 64] = (lid < 14) ? __float2half(a2) : __float2half(0.f);
}

// ---------------- fused: X = relu(bn(Y)) fp16  +  W^T convert (first 64 blocks) ----------
__global__ void bnw_kernel(const __half* __restrict__ Yin, __half* __restrict__ Xout,
                           const float* __restrict__ stats, const float* __restrict__ gamma,
                           const float* __restrict__ beta,
                           const float* __restrict__ W, __half* __restrict__ Wt) {
    __shared__ float ssc[128], ssh[128];
    int tid = threadIdx.x;
    if (blockIdx.x < 64) {                     // W^T fp16 convert folded in (K=128)
        int i = blockIdx.x * 256 + tid;
        int k = i >> 7, n = i & 127;
        Wt[n * 128 + k] = __float2half(W[k * 128 + n]);
    }
    if (tid < 128) {
        const float invn = 1.f / NN;
        float mu = stats[tid] * invn;
        float var = stats[128 + tid] * invn - mu * mu;
        float s = gamma[tid] * rsqrtf(var + 1e-5f);
        ssc[tid] = s;
        ssh[tid] = beta[tid] - mu * s;
    }
    __syncthreads();
    const __half2* Y2 = (const __half2*)Yin;
    __half2* X2 = (__half2*)Xout;
    int total = NN * 64;
    for (int i = blockIdx.x * blockDim.x + tid; i < total; i += gridDim.x * blockDim.x) {
        int c0 = (i & 63) * 2;
        float2 f = __half22float2(Y2[i]);
        float v0 = fmaxf(0.f, f.x * ssc[c0] + ssh[c0]);
        float v1 = fmaxf(0.f, f.y * ssc[c0 + 1] + ssh[c0 + 1]);
        X2[i] = __floats2half2_rn(v0, v1);
    }
}

// ---------------- mid-layer aggregation: t = 2*x[n] + sum_{src} x[src] -> fp16 -----------
// unroll-8 batched loads; pairwise HADD2 then fp32 accumulate
__global__ void agg_kernel(const __half* __restrict__ Xin, __half* __restrict__ Tout) {
    int w = (blockIdx.x * blockDim.x + threadIdx.x) >> 5;
    if (w >= NN) return;
    int lid = threadIdx.x & 31;
    const uint2* X2 = (const uint2*)Xin;   // 4 halves per uint2, 32 per row

    uint2 self = X2[(size_t)w * 32 + lid];
    float2 f0 = __half22float2(*(__half2*)&self.x);
    float2 f1 = __half22float2(*(__half2*)&self.y);
    float a0 = 2.f * f0.x, a1 = 2.f * f0.y, a2 = 2.f * f1.x, a3 = 2.f * f1.y;

    int beg = g_rowptr[w], end = g_rowptr[w + 1];
    int j = beg;
    for (; j + 8 <= end; j += 8) {
        int s[8];
#pragma unroll
        for (int u = 0; u < 8; ++u) s[u] = g_col[j + u];
        uint2 r[8];
#pragma unroll
        for (int u = 0; u < 8; ++u) r[u] = X2[(size_t)s[u] * 32 + lid];
#pragma unroll
        for (int u = 0; u < 8; u += 2) {
            __half2 p0 = __hadd2(*(__half2*)&r[u].x, *(__half2*)&r[u + 1].x);
            __half2 p1 = __hadd2(*(__half2*)&r[u].y, *(__half2*)&r[u + 1].y);
            float2 u0 = __half22float2(p0), u1 = __half22float2(p1);
            a0 += u0.x; a1 += u0.y; a2 += u1.x; a3 += u1.y;
        }
    }
    for (; j < end; ++j) {
        uint2 r0 = X2[(size_t)g_col[j] * 32 + lid];
        float2 u0 = __half22float2(*(__half2*)&r0.x);
        float2 u1 = __half22float2(*(__half2*)&r0.y);
        a0 += u0.x; a1 += u0.y; a2 += u1.x; a3 += u1.y;
    }
    uint2 o;
    *(__half2*)&o.x = __floats2half2_rn(a0, a1);
    *(__half2*)&o.y = __floats2half2_rn(a2, a3);
    ((uint2*)Tout)[(size_t)w * 32 + lid] = o;
}

// ---------------- readout: xg[g] = sum relu(bn(y)) over rows of graph g (gid sorted) -----
__global__ void readout_kernel(const __half* __restrict__ Yin, const int* __restrict__ gid,
                               float* __restrict__ xg, const float* __restrict__ stats,
                               const float* __restrict__ gamma, const float* __restrict__ beta) {
    __shared__ float ssc[128], ssh[128];
    int tid = threadIdx.x;       // 128 threads = one column each
    {
        const float invn = 1.f / NN;
        float mu = stats[tid] * invn;
        float var = stats[128 + tid] * invn - mu * mu;
        float s = gamma[tid] * rsqrtf(var + 1e-5f);
        ssc[tid] = s;
        ssh[tid] = beta[tid] - mu * s;
    }
    __syncthreads();
    int g = blockIdx.x;          // 2048 blocks
    int lo = 0, hi = NN;
    while (lo < hi) { int mid = (lo + hi) >> 1; if (gid[mid] < g) lo = mid + 1; else hi = mid; }
    int beg = lo;
    hi = NN;
    while (lo < hi) { int mid = (lo + hi) >> 1; if (gid[mid] < g + 1) lo = mid + 1; else hi = mid; }
    int end = lo;
    float sc = ssc[tid], sh = ssh[tid];
    float acc = 0.f;
    for (int r = beg; r < end; ++r)
        acc += fmaxf(0.f, __half2float(Yin[(size_t)r * 128 + tid]) * sc + sh);
    xg[(size_t)g * 128 + tid] = acc;
}

// ---------------- HMMA fp16 helper ----------------
__device__ __forceinline__ void mma16816(float c[4], uint32_t a0, uint32_t a1,
                                         uint32_t a2, uint32_t a3,
                                         uint32_t b0, uint32_t b1) {
    asm volatile(
        "mma.sync.aligned.m16n8k16.row.col.f32.f16.f16.f32 "
        "{%0,%1,%2,%3}, {%4,%5,%6,%7}, {%8,%9}, {%0,%1,%2,%3};"
        : "+f"(c[0]), "+f"(c[1]), "+f"(c[2]), "+f"(c[3])
        : "r"(a0), "r"(a1), "r"(a2), "r"(a3), "r"(b0), "r"(b1));
}

// ---------------- tensor GEMM: y[rows,128] = T[rows,K] @ W[K,128] + bscale*b ------------
// fp16 single-term, single K-stage, templated K (80 for layer 0, 128 for layers 1-4).
// 128x128 CTA tile, 8 warps as 4(m)x2(n). Fused bias + BN stats; y stored fp16.
#define PITCH 136
template <int KD>
__global__ void __launch_bounds__(256, 2) gemm_mma_kernel(
    const __half* __restrict__ T, const __half* __restrict__ Wt,
    const float* __restrict__ bias, float bscale,
    __half* __restrict__ Y, float* __restrict__ stats) {
    extern __shared__ char smem[];
    __half* Ah = (__half*)smem;                 // [128][PITCH]
    __half* Bh = Ah + 128 * PITCH;              // [128][PITCH]
    float* sbias = (float*)(Bh + 128 * PITCH);  // 128
    float* sstat = sbias + 128;                 // 256 (sum|sq)

    int tid = threadIdx.x;
    int lane = tid & 31, wid = tid >> 5;
    int q = lane & 3, rsel = lane >> 2;
    int mw = wid & 3, nw = wid >> 2;
    int m0 = mw * 32, n0 = nw * 64;
    int row0 = blockIdx.x * 128;

    if (tid < 128) sbias[tid] = bscale * bias[tid];
    sstat[tid] = 0.f;

    // load A tile [128][KD] fp16 (KD/8 uint4 per row) and B tile [128][KD]
    constexpr int CHUNKS = KD / 8;
    for (int idx = tid; idx < 128 * CHUNKS; idx += 256) {
        int r = idx / CHUNKS, c8 = idx % CHUNKS;
        int gr = row0 + r;
        uint4 v = make_uint4(0u, 0u, 0u, 0u);
        if (gr < NN) v = *(const uint4*)&T[(size_t)gr * 128 + c8 * 8];
        *(uint4*)&Ah[r * PITCH + c8 * 8] = v;
    }
    for (int idx = tid; idx < 128 * CHUNKS; idx += 256) {
        int r = idx / CHUNKS, c8 = idx % CHUNKS;
        *(uint4*)&Bh[r * PITCH + c8 * 8] = *(const uint4*)&Wt[r * 128 + c8 * 8];
    }
    __syncthreads();

    float acc[2][8][4];
#pragma unroll
    for (int i = 0; i < 2; ++i)
#pragma unroll
        for (int j = 0; j < 8; ++j)
#pragma unroll
            for (int p = 0; p < 4; ++p) acc[i][j][p] = 0.f;

#pragma unroll
    for (int ks = 0; ks < KD; ks += 16) {
        uint32_t a[2][4];
#pragma unroll
        for (int i = 0; i < 2; ++i) {
            const __half* ar = Ah + (m0 + i * 16 + rsel) * PITCH + ks + 2 * q;
            a[i][0] = *(const uint32_t*)ar;
            a[i][1] = *(const uint32_t*)(ar + 8 * PITCH);
            a[i][2] = *(const uint32_t*)(ar + 8);
            a[i][3] = *(const uint32_t*)(ar + 8 * PITCH + 8);
        }
#pragma unroll
        for (int j = 0; j < 8; ++j) {
            const __half* br = Bh + (n0 + j * 8 + rsel) * PITCH + ks + 2 * q;
            uint32_t b0 = *(const uint32_t*)br;
            uint32_t b1 = *(const uint32_t*)(br + 8);
            mma16816(acc[0][j], a[0][0], a[0][1], a[0][2], a[0][3], b0, b1);
            mma16816(acc[1][j], a[1][0], a[1][1], a[1][2], a[1][3], b0, b1);
        }
    }

    // epilogue: bias, fp16 store, BN stats (from exact fp32 values)
#pragma unroll
    for (int i = 0; i < 2; ++i) {
        int r_lo = row0 + m0 + i * 16 + rsel, r_hi = r_lo + 8;
        bool vlo = r_lo < NN, vhi = r_hi < NN;
#pragma unroll
        for (int j = 0; j < 8; ++j) {
            int c0 = n0 + j * 8 + 2 * q;
            float b0 = sbias[c0], b1 = sbias[c0 + 1];
            float v00 = vlo ? acc[i][j][0] + b0 : 0.f;
            float v01 = vlo ? acc[i][j][1] + b1 : 0.f;
            float v10 = vhi ? acc[i][j][2] + b0 : 0.f;
            float v11 = vhi ? acc[i][j][3] + b1 : 0.f;
            if (vlo) *(__half2*)&Y[(size_t)r_lo * 128 + c0] = __floats2half2_rn(v00, v01);
            if (vhi) *(__half2*)&Y[(size_t)r_hi * 128 + c0] = __floats2half2_rn(v10, v11);
            float s0 = v00 + v10, s1 = v01 + v11;
            float q0 = v00 * v00 + v10 * v10, q1 = v01 * v01 + v11 * v11;
#pragma unroll
            for (int off = 4; off <= 16; off <<= 1) {
                s0 += __shfl_xor_sync(0xFFFFFFFFu, s0, off);
                s1 += __shfl_xor_sync(0xFFFFFFFFu, s1, off);
                q0 += __shfl_xor_sync(0xFFFFFFFFu, q0, off);
                q1 += __shfl_xor_sync(0xFFFFFFFFu, q1, off);
            }
            if (rsel == 0) {
                atomicAdd(&sstat[c0], s0);
                atomicAdd(&sstat[c0 + 1], s1);
                atomicAdd(&sstat[128 + c0], q0);
                atomicAdd(&sstat[128 + c0 + 1], q1);
            }
        }
    }
    __syncthreads();
    atomicAdd(&stats[tid], sstat[tid]);
}

// ---------------- small MLP GEMM (thread-per-output) ----------------
__global__ void gemm_small_kernel(const float* __restrict__ X, const float* __restrict__ W,
                                  const float* __restrict__ bias, int R, int K, int C,
                                  float* __restrict__ Y, float* __restrict__ stats) {
    int c = blockIdx.x * 32 + (threadIdx.x & 31);
    int r = blockIdx.y * 8 + (threadIdx.x >> 5);
    if (c >= C || r >= R) return;
    float acc = bias[c];
    const float* xr = X + (size_t)r * K;
    for (int k = 0; k < K; ++k) acc = fmaf(xr[k], W[(size_t)k * C + c], acc);
    Y[(size_t)r * C + c] = acc;
    atomicAdd(&stats[c], acc);
    atomicAdd(&stats[C + c], acc * acc);
}

// norm+relu with BN finalize folded in
__global__ void norm_relu_kernel(float* __restrict__ Y, const float* __restrict__ stats,
                                 const float* __restrict__ gamma, const float* __restrict__ beta,
                                 float invn, int total, int C) {
    int i = blockIdx.x * blockDim.x + threadIdx.x;
    if (i >= total) return;
    int c = i % C;
    float mu = stats[c] * invn;
    float var = stats[C + c] * invn - mu * mu;
    float s = gamma[c] * rsqrtf(var + 1e-5f);
    float v = (Y[i] - mu) * s + beta[c];
    Y[i] = fmaxf(v, 0.f);
}

__global__ void fc2_kernel(const float* __restrict__ X, const float* __restrict__ W,
                           const float* __restrict__ bias, float* __restrict__ out) {
    int c = blockIdx.x * 32 + (threadIdx.x & 31);
    int g = blockIdx.y * 8 + (threadIdx.x >> 5);
    if (c >= NCOUT || g >= GG) return;
    float acc = bias[204 + c];
    const float* xr = X + (size_t)g * 256;
    for (int k = 0; k < 256; ++k) acc = fmaf(xr[k], W[(size_t)k * 408 + 204 + c], acc);
    out[(size_t)g * NCOUT + c] = 1.f / (1.f + expf(-acc));
}

// ---------------- host orchestration ----------------
extern "C" void kernel_launch(void* const* d_in, const int* in_sizes, int n_in,
                              void* d_out, int out_size) {
    const float* h        = (const float*)d_in[0];
    const int*   esrc     = (const int*)d_in[1];
    const int*   edst     = (const int*)d_in[2];
    const int*   gid      = (const int*)d_in[3];
    const float* W1       = (const float*)d_in[4];
    const float* b1       = (const float*)d_in[5];
    const float* g1_gamma = (const float*)d_in[6];
    const float* g1_beta  = (const float*)d_in[7];
    const float* Wg       = (const float*)d_in[8];
    const float* bg       = (const float*)d_in[9];
    const float* gg       = (const float*)d_in[10];
    const float* gb       = (const float*)d_in[11];
    const float* fc1_W    = (const float*)d_in[12];
    const float* fc1_b    = (const float*)d_in[13];
    const float* bn1_g    = (const float*)d_in[14];
    const float* bn1_b    = (const float*)d_in[15];
    const float* lin_W    = (const float*)d_in[16];
    const float* lin_b    = (const float*)d_in[17];
    const float* lbn_g    = (const float*)d_in[18];
    const float* lbn_b    = (const float*)d_in[19];
    const float* fc2_W    = (const float*)d_in[20];
    const float* fc2_b    = (const float*)d_in[21];
    float* out = (float*)d_out;

    float *stats, *xg, *m1, *m2;
    __half *bufT, *bufY, *bufX, *wt;
    int *rowptr;
    cudaGetSymbolAddress((void**)&bufT, g_bufT);
    cudaGetSymbolAddress((void**)&bufY, g_bufY);
    cudaGetSymbolAddress((void**)&bufX, g_bufX);
    cudaGetSymbolAddress((void**)&stats, g_stats);
    cudaGetSymbolAddress((void**)&xg, g_xg);
    cudaGetSymbolAddress((void**)&m1, g_m1);
    cudaGetSymbolAddress((void**)&m2, g_m2);
    cudaGetSymbolAddress((void**)&rowptr, g_rowptr);
    cudaGetSymbolAddress((void**)&wt, g_wt);

    const int SMEMMA = 2 * 128 * PITCH * 2 + 128 * 4 + 256 * 4;   // 71168
    cudaFuncSetAttribute(gemm_mma_kernel<80>, cudaFuncAttributeMaxDynamicSharedMemorySize, SMEMMA);
    cudaFuncSetAttribute(gemm_mma_kernel<128>, cudaFuncAttributeMaxDynamicSharedMemorySize, SMEMMA);

    const int WB = (NN * 32 + 255) / 256;   // warp-per-node grids
    const int EB = (EE + 255) / 256;
    const int GBt = (NN + 127) / 128;       // 782 GEMM tiles
    const int BNB = 6250;

    // ---- CSR build + layer 0 (K=78 padded to 80) ----
    wcvt_kernel<<<64, 256>>>(W1, 78, wt, 1);     // also zeroes rowptr + stats
    hist_kernel<<<EB, 256>>>(edst);              // also zeroes cursor
    scan_kernel<<<1, 1024>>>(rowptr, NN + 1);
    fill_kernel<<<EB, 256>>>(esrc, edst);
    agg0_kernel<<<WB, 256>>>(h);
    gemm_mma_kernel<80><<<GBt, 256, SMEMMA>>>(bufT, wt, b1, 2.f, bufY, stats);

    // ---- layers 1..4: bnw (X + next W^T) -> agg -> gemm ----
    const float* gmas[5] = {g1_gamma, gg, gg + 128, gg + 256, gg + 384};
    const float* btas[5] = {g1_beta,  gb, gb + 128, gb + 256, gb + 384};
    for (int l = 0; l < 4; ++l) {
        float* stPrev = stats + l * 1024;
        float* st = stats + (l + 1) * 1024;
        bnw_kernel<<<BNB, 256>>>(bufY, bufX, stPrev, gmas[l], btas[l],
                                 Wg + (size_t)l * 128 * 128, wt);
        agg_kernel<<<WB, 256>>>(bufX, bufT);
        gemm_mma_kernel<128><<<GBt, 256, SMEMMA>>>(bufT, wt, bg + l * 128, 2.f, bufY, st);
    }

    // ---- fused BN + sorted segment-sum readout ----
    readout_kernel<<<GG, 128>>>(bufY, gid, xg, stats + 4 * 1024, gmas[4], btas[4]);

    // ---- MLP head ----
    float* st5 = stats + 5 * 1024;
    float* st6 = stats + 6 * 1024;
    gemm_small_kernel<<<dim3(512 / 32, GG / 8), 256>>>(xg, fc1_W, fc1_b, GG, 128, 512, m1, st5);
    norm_relu_kernel<<<(GG * 512 + 255) / 256, 256>>>(m1, st5, bn1_g, bn1_b, 1.f / GG,
                                                      GG * 512, 512);

    gemm_small_kernel<<<dim3(256 / 32, GG / 8), 256>>>(m1, lin_W, lin_b, GG, 512, 256, m2, st6);
    norm_relu_kernel<<<(GG * 256 + 255) / 256, 256>>>(m2, st6, lbn_g, lbn_b, 1.f / GG,
                                                      GG * 256, 256);

    fc2_kernel<<<dim3(7, GG / 8), 256>>>(m2, fc2_W, fc2_b, out);
}